// round 16
// baseline (speedup 1.0000x reference)
#include <cuda_runtime.h>
#include <math.h>
#include <stdint.h>

// Problem constants
#define Bb   8
#define Nn   2048
#define Mm   1024
#define BM   8192          // B*M
#define Kk   64
#define Ff   64
#define C0c  67
#define C1c  64
#define C2c  128

// Output layout (float32, concatenated reference outputs)
#define OFF_POS   1048576   // BM*C2
#define OFF_BATCH 1073152   // + BM*3
#define OFF_IDX   1081344   // + BM

// ---------------- device scratch (static, no allocation) ----------------
__device__ int   g_idxLoc[BM];
__device__ float g_qpos[BM * 3];
__device__ int   g_nbr[BM * Kk];
__device__ int   g_cnt[BM];
__device__ int   g_V;
// h1 stored TRANSPOSED: [bm][c][k]  (c = channel 0..63, k = edge 0..63)
__device__ float g_h1[BM * Kk * C1c];           // 128 MB
__device__ float g_hmax[BM * C2c];              // masked max of h2 (pre-BN)
__device__ float g_hmin[BM * C2c];              // masked min of h2 (pre-BN)
__device__ float g_ps1[BM * C1c], g_pq1[BM * C1c];
__device__ float g_ps2[BM * C2c], g_pq2[BM * C2c];
__device__ float g_a1[C1c], g_o1[C1c], g_a2[C2c], g_o2[C2c];

// Strict (non-contracted) squared distance — must match XLA's fp32 mul/add
__device__ __forceinline__ float dist2s(float ax, float ay, float az,
                                        float bx, float by, float bz) {
    float dx = ax - bx, dy = ay - by, dz = az - bz;
    return __fadd_rn(__fadd_rn(__fmul_rn(dx, dx), __fmul_rn(dy, dy)),
                     __fmul_rn(dz, dz));
}

// Packed fp32x2 FMA (Blackwell sm_100+; per-lane .rn — bitwise == scalar fmaf)
#define FMA_F32X2(d, a, b, c) \
    asm("fma.rn.f32x2 %0, %1, %2, %3;" : "=l"(d) : "l"(a), "l"(b), "l"(c))
#define PACK2(d, v) \
    asm("mov.b64 %0, {%1, %1};" : "=l"(d) : "r"(__float_as_uint(v)))
#define UNPACK2(lo, hi, p) do {                                              \
    unsigned _ulo, _uhi;                                                     \
    asm("mov.b64 {%0, %1}, %2;" : "=r"(_ulo), "=r"(_uhi) : "l"(p));          \
    lo = __uint_as_float(_ulo); hi = __uint_as_float(_uhi);                  \
} while (0)

#define U64MAX(a, b) (((a) > (b)) ? (a) : (b))

// ---------------- K1: farthest point sampling (1 block / batch) ----------------
// 512 threads, 4 points/thread. NO smem atomics (the old single-address
// atomicMax serialized 16 warps at ~32cyc each = ~512 cyc/iter):
//   - per-warp: redux.max on value bits, redux.min on tying global index;
//     lane 0 STS's the packed (value, Nn-idx) key to its warp slot.
//   - one barrier; then EVERY thread loads all 16 slots (8 broadcast
//     LDS.128) and computes the block max via a u64 tree — no 2nd barrier.
//   - slots double-buffered by t&1: same-buffer reuse is 2 barriers apart.
// Tie semantics identical to stable argmax (max value, lowest index).
__global__ void __launch_bounds__(512) k_fps(const float* __restrict__ pos) {
    const int b = blockIdx.x;
    const int tid = threadIdx.x;
    __shared__ float4 sxyz[Nn];
    __shared__ __align__(16) unsigned long long skey[2][16];

    const float* p = pos + (size_t)b * Nn * 3;
    for (int i = tid; i < Nn; i += 512) {
        sxyz[i] = make_float4(p[i * 3 + 0], p[i * 3 + 1], p[i * 3 + 2], 0.f);
    }
    __syncthreads();

    const int i0 = tid, i1 = tid + 512, i2 = tid + 1024, i3 = tid + 1536;
    const float4 p0 = sxyz[i0], p1 = sxyz[i1], p2 = sxyz[i2], p3 = sxyz[i3];

    float4 c = sxyz[0];
    float m0 = dist2s(p0.x, p0.y, p0.z, c.x, c.y, c.z);
    float m1 = dist2s(p1.x, p1.y, p1.z, c.x, c.y, c.z);
    float m2 = dist2s(p2.x, p2.y, p2.z, c.x, c.y, c.z);
    float m3 = dist2s(p3.x, p3.y, p3.z, c.x, c.y, c.z);

    if (tid == 0) {
        g_idxLoc[b * Mm] = 0;
        float* qp = g_qpos + (size_t)(b * Mm) * 3;
        qp[0] = c.x; qp[1] = c.y; qp[2] = c.z;
    }
    const int wid = tid >> 5;
    const int lane = tid & 31;

    for (int t = 1; t < Mm; ++t) {
        // value-only local tournament (FMNMX)
        float bv = fmaxf(fmaxf(m0, m1), fmaxf(m2, m3));
        unsigned vbits = __float_as_uint(bv);   // distances >= 0: monotone as u32
        unsigned rv;
        asm("redux.sync.max.u32 %0, %1, 0xffffffff;" : "=r"(rv) : "r"(vbits));
        // lowest local index holding the max (i0 < i1 < i2 < i3)
        int bi = (m0 == bv) ? i0 : (m1 == bv) ? i1 : (m2 == bv) ? i2 : i3;
        unsigned cand = (vbits == rv) ? (unsigned)bi : 0xffffffffu;
        unsigned ri;
        asm("redux.sync.min.u32 %0, %1, 0xffffffff;" : "=r"(ri) : "r"(cand));
        unsigned long long* buf = skey[t & 1];
        if (lane == 0) {
            buf[wid] = ((unsigned long long)rv << 32) |
                       (unsigned)(Nn - (int)ri);
        }
        __syncthreads();
        // block max over 16 per-warp keys (broadcast LDS.128, 15-op tree)
        const ulonglong2* kp = (const ulonglong2*)buf;
        ulonglong2 k0 = kp[0], k1 = kp[1], k2 = kp[2], k3 = kp[3];
        ulonglong2 k4 = kp[4], k5 = kp[5], k6 = kp[6], k7 = kp[7];
        unsigned long long a0 = U64MAX(k0.x, k0.y), a1 = U64MAX(k1.x, k1.y);
        unsigned long long a2 = U64MAX(k2.x, k2.y), a3 = U64MAX(k3.x, k3.y);
        unsigned long long a4 = U64MAX(k4.x, k4.y), a5 = U64MAX(k5.x, k5.y);
        unsigned long long a6 = U64MAX(k6.x, k6.y), a7 = U64MAX(k7.x, k7.y);
        unsigned long long b0 = U64MAX(a0, a1), b1 = U64MAX(a2, a3);
        unsigned long long b2 = U64MAX(a4, a5), b3 = U64MAX(a6, a7);
        unsigned long long best = U64MAX(U64MAX(b0, b1), U64MAX(b2, b3));
        int nxt = Nn - (int)(unsigned int)(best & 0xffffffffu);
        c = sxyz[nxt];                             // one LDS.128 broadcast
        if (tid == 0) {
            g_idxLoc[b * Mm + t] = nxt;
            float* qp = g_qpos + (size_t)(b * Mm + t) * 3;
            qp[0] = c.x; qp[1] = c.y; qp[2] = c.z;
        }
        m0 = fminf(m0, dist2s(p0.x, p0.y, p0.z, c.x, c.y, c.z));
        m1 = fminf(m1, dist2s(p1.x, p1.y, p1.z, c.x, c.y, c.z));
        m2 = fminf(m2, dist2s(p2.x, p2.y, p2.z, c.x, c.y, c.z));
        m3 = fminf(m3, dist2s(p3.x, p3.y, p3.z, c.x, c.y, c.z));
    }
}

// ---------------- K2: ball query, first K in index order (1 warp / center) ----------------
__global__ void __launch_bounds__(256) k_ball(const float* __restrict__ pos) {
    int gw = (blockIdx.x * blockDim.x + threadIdx.x) >> 5;
    if (gw >= BM) return;
    const int lane = threadIdx.x & 31;
    const int b = gw >> 10;
    const float* p = pos + (size_t)b * Nn * 3;
    const float qx = g_qpos[gw * 3 + 0];
    const float qy = g_qpos[gw * 3 + 1];
    const float qz = g_qpos[gw * 3 + 2];
    int cnt = 0;
    for (int base = 0; base < Nn; base += 32) {
        int i = base + lane;
        float px = p[i * 3 + 0], py = p[i * 3 + 1], pz = p[i * 3 + 2];
        float d2 = dist2s(px, py, pz, qx, qy, qz);
        bool in = (d2 <= 0.04f);   // float32(R*R), same promotion as reference
        unsigned mask = __ballot_sync(0xffffffffu, in);
        int pre = __popc(mask & ((1u << lane) - 1u));
        int pp2 = cnt + pre;
        if (in && pp2 < Kk) g_nbr[gw * Kk + pp2] = i;
        cnt += __popc(mask);
        if (cnt >= Kk) break;
    }
    if (lane == 0) g_cnt[gw] = (cnt < Kk) ? cnt : Kk;
}

// ---------------- count total valid edges ----------------
__global__ void __launch_bounds__(256) k_count() {
    __shared__ int sr[256];
    int tid = threadIdx.x;
    int s = 0;
    for (int i = tid; i < BM; i += 256) s += g_cnt[i];
    sr[tid] = s; __syncthreads();
    for (int st = 128; st; st >>= 1) {
        if (tid < st) sr[tid] += sr[tid + st];
        __syncthreads();
    }
    if (tid == 0) g_V = sr[0];
}

// ---------------- K3: layer-1 (67->64) + partial BN1 stats ----------------
// R8's measured-best form (149.6us): 256 thr; tile 4c x 4e; pipelined j-loop.
#define FT_STRIDE 68
#define RED1_STR  68
__global__ void __launch_bounds__(256, 5) k_layer1(
    const float* __restrict__ x, const float* __restrict__ pos,
    const float* __restrict__ W1, const float* __restrict__ b1) {
    extern __shared__ float smem[];
    float* featT = smem;                        // [67][68] = 4556 floats
    float* W1s   = featT + C0c * FT_STRIDE;     // [67][64]
    float* redS  = featT;                       // alias: [16][68]
    float* redQ  = featT + 16 * RED1_STR;       // alias: [16][68]
    __shared__ int snbr[Kk];

    const int bm = blockIdx.x;
    const int b = bm >> 10;
    const int tid = threadIdx.x;
    const int cnt = g_cnt[bm];

    if (tid < Kk) snbr[tid] = (tid < cnt) ? g_nbr[bm * Kk + tid] : 0;
    for (int e = tid; e < C0c * C1c; e += 256) W1s[e] = W1[e];
    __syncthreads();

    const float* xb = x + (size_t)b * Nn * Ff;
    for (int e = tid; e < cnt * Ff; e += 256) {
        int k = e >> 6, j = e & 63;
        featT[j * FT_STRIDE + k] = xb[(size_t)snbr[k] * Ff + j];
    }
    if (tid < cnt) {
        int k = tid, n = snbr[k];
        const float* pp = pos + ((size_t)b * Nn + n) * 3;
        const float* qq = g_qpos + (size_t)bm * 3;
        featT[64 * FT_STRIDE + k] = pp[0] - qq[0];
        featT[65 * FT_STRIDE + k] = pp[1] - qq[1];
        featT[66 * FT_STRIDE + k] = pp[2] - qq[2];
    }
    __syncthreads();

    const int eg = (tid & 15) * 4;
    const int cg = (tid >> 4) * 4;
    float ps[4] = {0.f, 0.f, 0.f, 0.f};
    float pq[4] = {0.f, 0.f, 0.f, 0.f};
    if (eg < cnt) {
        unsigned long long acc[8];
        float4 b4 = *(const float4*)(b1 + cg);
        PACK2(acc[0], b4.x); acc[1] = acc[0];
        PACK2(acc[2], b4.y); acc[3] = acc[2];
        PACK2(acc[4], b4.z); acc[5] = acc[4];
        PACK2(acc[6], b4.w); acc[7] = acc[6];
        const float* wr = W1s + cg;
        const float* fr = featT + eg;
        float4 w4 = *(const float4*)(wr);
        ulonglong2 f = *(const ulonglong2*)(fr);
        #pragma unroll 4
        for (int j = 0; j < C0c - 1; j++) {
            float4 w4n = *(const float4*)(wr + (j + 1) * C1c);
            ulonglong2 fn = *(const ulonglong2*)(fr + (j + 1) * FT_STRIDE);
            unsigned long long w0, w1, w2, w3;
            PACK2(w0, w4.x); PACK2(w1, w4.y); PACK2(w2, w4.z); PACK2(w3, w4.w);
            FMA_F32X2(acc[0], f.x, w0, acc[0]);
            FMA_F32X2(acc[1], f.y, w0, acc[1]);
            FMA_F32X2(acc[2], f.x, w1, acc[2]);
            FMA_F32X2(acc[3], f.y, w1, acc[3]);
            FMA_F32X2(acc[4], f.x, w2, acc[4]);
            FMA_F32X2(acc[5], f.y, w2, acc[5]);
            FMA_F32X2(acc[6], f.x, w3, acc[6]);
            FMA_F32X2(acc[7], f.y, w3, acc[7]);
            w4 = w4n; f = fn;
        }
        {   // tail j = C0c-1
            unsigned long long w0, w1, w2, w3;
            PACK2(w0, w4.x); PACK2(w1, w4.y); PACK2(w2, w4.z); PACK2(w3, w4.w);
            FMA_F32X2(acc[0], f.x, w0, acc[0]);
            FMA_F32X2(acc[1], f.y, w0, acc[1]);
            FMA_F32X2(acc[2], f.x, w1, acc[2]);
            FMA_F32X2(acc[3], f.y, w1, acc[3]);
            FMA_F32X2(acc[4], f.x, w2, acc[4]);
            FMA_F32X2(acc[5], f.y, w2, acc[5]);
            FMA_F32X2(acc[6], f.x, w3, acc[6]);
            FMA_F32X2(acc[7], f.y, w3, acc[7]);
        }
        float* outb = g_h1 + (size_t)bm * (Kk * C1c);
        #pragma unroll
        for (int ch = 0; ch < 4; ch++) {
            float h0, h1, h2, h3;
            UNPACK2(h0, h1, acc[2 * ch]);
            UNPACK2(h2, h3, acc[2 * ch + 1]);
            h0 = fmaxf(h0, 0.f); h1 = fmaxf(h1, 0.f);
            h2 = fmaxf(h2, 0.f); h3 = fmaxf(h3, 0.f);
            *(float4*)(outb + (cg + ch) * Kk + eg) = make_float4(h0, h1, h2, h3);
            float hv[4] = {h0, h1, h2, h3};
            #pragma unroll
            for (int t = 0; t < 4; t++) {
                if (eg + t < cnt) { ps[ch] += hv[t]; pq[ch] += hv[t] * hv[t]; }
            }
        }
    }
    __syncthreads();   // all featT reads done before aliased red writes
    *(float4*)(redS + (tid & 15) * RED1_STR + cg) = make_float4(ps[0], ps[1], ps[2], ps[3]);
    *(float4*)(redQ + (tid & 15) * RED1_STR + cg) = make_float4(pq[0], pq[1], pq[2], pq[3]);
    __syncthreads();
    if (tid < C1c) {
        float s = 0.f, q = 0.f;
        #pragma unroll
        for (int g = 0; g < 16; g++) {
            s += redS[g * RED1_STR + tid];
            q += redQ[g * RED1_STR + tid];
        }
        g_ps1[(size_t)bm * C1c + tid] = s;
        g_pq1[(size_t)bm * C1c + tid] = q;
    }
}

// ---------------- BN stat reduction (deterministic, double) ----------------
template <int C>
__global__ void __launch_bounds__(256) k_bnstat(const float* __restrict__ gamma,
                                                const float* __restrict__ beta) {
    const float* ps = (C == C1c) ? g_ps1 : g_ps2;
    const float* pq = (C == C1c) ? g_pq1 : g_pq2;
    float* a = (C == C1c) ? g_a1 : g_a2;
    float* o = (C == C1c) ? g_o1 : g_o2;
    const int c = blockIdx.x, tid = threadIdx.x;
    __shared__ double ss[256], sq[256];
    double s = 0.0, q = 0.0;
    for (int i = tid; i < BM; i += 256) {
        s += (double)ps[(size_t)i * C + c];
        q += (double)pq[(size_t)i * C + c];
    }
    ss[tid] = s; sq[tid] = q; __syncthreads();
    for (int st = 128; st; st >>= 1) {
        if (tid < st) { ss[tid] += ss[tid + st]; sq[tid] += sq[tid + st]; }
        __syncthreads();
    }
    if (tid == 0) {
        double V = (double)g_V;
        double mean = ss[0] / V;
        double var = sq[0] / V - mean * mean;
        float af = gamma[c] * rsqrtf((float)var + 1e-5f);
        a[c] = af;
        o[c] = beta[c] - (float)mean * af;
    }
}

// ---------------- K5: BN1-apply + layer-2 (64->128) + BN2 stats + pooled extremes ----------
// R15's measured-best form: 512 thr, tile 4c x 4e, reduction buffers aliased
// over h1ns => 50.2 KB smem, 4 blocks/SM (100% occ), regs 32 ((512,4)).
#define RED2_STR 132
__global__ void __launch_bounds__(512, 4) k_layer2(const float* __restrict__ W2,
                                                   const float* __restrict__ b2) {
    extern __shared__ float smem[];
    float* h1ns = smem;                         // [64][68] = 4352 floats
    float* W2s  = h1ns + C1c * FT_STRIDE;       // [64][128]
    float* redA = h1ns;                         // alias: [16][132] = 2112
    float* redB = h1ns + 16 * RED2_STR;         // alias: 2112 (4224 <= 4352 ok)
    __shared__ float a1s[C1c], o1s[C1c];

    const int bm = blockIdx.x;
    const int tid = threadIdx.x;
    const int cnt = g_cnt[bm];

    if (tid < C1c) { a1s[tid] = g_a1[tid]; o1s[tid] = g_o1[tid]; }
    for (int e = tid; e < C1c * C2c; e += 512) W2s[e] = W2[e];
    __syncthreads();

    const float* h1p = g_h1 + (size_t)bm * (Kk * C1c);   // [j][k] layout
    for (int e = tid; e < C1c * Kk; e += 512) {
        int j = e >> 6, k = e & 63;
        h1ns[j * FT_STRIDE + k] = h1p[e] * a1s[j] + o1s[j];   // conflict-free STS
    }
    __syncthreads();

    const int eg = (tid & 15) * 4;
    const int cg = (tid >> 4) * 4;          // 0..124
    float ps[4]  = {0.f, 0.f, 0.f, 0.f};
    float pq[4]  = {0.f, 0.f, 0.f, 0.f};
    float pmx[4] = {-INFINITY, -INFINITY, -INFINITY, -INFINITY};
    float pmn[4] = { INFINITY,  INFINITY,  INFINITY,  INFINITY};
    if (eg < cnt) {
        unsigned long long acc[8];
        float4 b4 = *(const float4*)(b2 + cg);
        PACK2(acc[0], b4.x); acc[1] = acc[0];
        PACK2(acc[2], b4.y); acc[3] = acc[2];
        PACK2(acc[4], b4.z); acc[5] = acc[4];
        PACK2(acc[6], b4.w); acc[7] = acc[6];
        #pragma unroll 4
        for (int j = 0; j < C1c; j++) {
            float4 w4 = *(const float4*)(W2s + j * C2c + cg);
            ulonglong2 f = *(const ulonglong2*)(h1ns + j * FT_STRIDE + eg);
            unsigned long long w0, w1, w2, w3;
            PACK2(w0, w4.x); PACK2(w1, w4.y); PACK2(w2, w4.z); PACK2(w3, w4.w);
            FMA_F32X2(acc[0], f.x, w0, acc[0]);
            FMA_F32X2(acc[1], f.y, w0, acc[1]);
            FMA_F32X2(acc[2], f.x, w1, acc[2]);
            FMA_F32X2(acc[3], f.y, w1, acc[3]);
            FMA_F32X2(acc[4], f.x, w2, acc[4]);
            FMA_F32X2(acc[5], f.y, w2, acc[5]);
            FMA_F32X2(acc[6], f.x, w3, acc[6]);
            FMA_F32X2(acc[7], f.y, w3, acc[7]);
        }
        #pragma unroll
        for (int ch = 0; ch < 4; ch++) {
            float h0, h1, h2, h3;
            UNPACK2(h0, h1, acc[2 * ch]);
            UNPACK2(h2, h3, acc[2 * ch + 1]);
            float hv[4] = {fmaxf(h0, 0.f), fmaxf(h1, 0.f),
                           fmaxf(h2, 0.f), fmaxf(h3, 0.f)};
            #pragma unroll
            for (int t = 0; t < 4; t++) {
                if (eg + t < cnt) {
                    ps[ch] += hv[t]; pq[ch] += hv[t] * hv[t];
                    pmx[ch] = fmaxf(pmx[ch], hv[t]);
                    pmn[ch] = fminf(pmn[ch], hv[t]);
                }
            }
        }
    }
    // round 1: sum & sumsq (red aliases h1ns — barrier after last h1ns read)
    __syncthreads();
    *(float4*)(redA + (tid & 15) * RED2_STR + cg) = make_float4(ps[0], ps[1], ps[2], ps[3]);
    *(float4*)(redB + (tid & 15) * RED2_STR + cg) = make_float4(pq[0], pq[1], pq[2], pq[3]);
    __syncthreads();
    if (tid < C2c) {
        float s = 0.f, q = 0.f;
        #pragma unroll
        for (int g = 0; g < 16; g++) {
            s += redA[g * RED2_STR + tid];
            q += redB[g * RED2_STR + tid];
        }
        g_ps2[(size_t)bm * C2c + tid] = s;
        g_pq2[(size_t)bm * C2c + tid] = q;
    }
    __syncthreads();
    // round 2: max & min
    *(float4*)(redA + (tid & 15) * RED2_STR + cg) = make_float4(pmx[0], pmx[1], pmx[2], pmx[3]);
    *(float4*)(redB + (tid & 15) * RED2_STR + cg) = make_float4(pmn[0], pmn[1], pmn[2], pmn[3]);
    __syncthreads();
    if (tid < C2c) {
        float mx = -INFINITY, mn = INFINITY;
        #pragma unroll
        for (int g = 0; g < 16; g++) {
            mx = fmaxf(mx, redA[g * RED2_STR + tid]);
            mn = fminf(mn, redB[g * RED2_STR + tid]);
        }
        g_hmax[(size_t)bm * C2c + tid] = mx;
        g_hmin[(size_t)bm * C2c + tid] = mn;
    }
}

// ---------------- K7: pooled BN2-apply ----------------
// max_k(a*h+o) == a*max_k(h)+o for a>=0, a*min_k(h)+o for a<0 (monotone fp ops,
// bitwise identical to elementwise-then-max). cnt>=1 always (center in-ball).
__global__ void __launch_bounds__(128) k_pool(float* __restrict__ out) {
    const int bm = blockIdx.x;
    const int c = threadIdx.x;
    const float a = g_a2[c], o = g_o2[c];
    const float h = (a >= 0.f) ? g_hmax[(size_t)bm * C2c + c]
                               : g_hmin[(size_t)bm * C2c + c];
    out[(size_t)bm * C2c + c] = a * h + o;
}

// ---------------- meta outputs: pos_out, batch_out, idx_glob ----------------
__global__ void __launch_bounds__(256) k_meta(float* __restrict__ out) {
    int i = blockIdx.x * blockDim.x + threadIdx.x;
    if (i >= BM) return;
    int b = i >> 10;
    out[OFF_POS + i * 3 + 0] = g_qpos[i * 3 + 0];
    out[OFF_POS + i * 3 + 1] = g_qpos[i * 3 + 1];
    out[OFF_POS + i * 3 + 2] = g_qpos[i * 3 + 2];
    out[OFF_BATCH + i] = (float)b;
    out[OFF_IDX + i] = (float)(g_idxLoc[i] + b * Nn);
}

// ---------------- host launcher ----------------
extern "C" void kernel_launch(void* const* d_in, const int* in_sizes, int n_in,
                              void* d_out, int out_size) {
    const float* x   = (const float*)d_in[0];
    const float* pos = (const float*)d_in[1];
    // d_in[2] = batch (unused; recomputed analytically)
    const float* W1  = (const float*)d_in[3];
    const float* b1  = (const float*)d_in[4];
    const float* g1  = (const float*)d_in[5];
    const float* be1 = (const float*)d_in[6];
    const float* W2  = (const float*)d_in[7];
    const float* b2  = (const float*)d_in[8];
    const float* g2  = (const float*)d_in[9];
    const float* be2 = (const float*)d_in[10];
    float* out = (float*)d_out;

    const int smem1 = (C0c * FT_STRIDE + C0c * C1c) * (int)sizeof(float);   // 35.4 KB
    const int smem2 = (C1c * FT_STRIDE + C1c * C2c) * (int)sizeof(float);   // 50.2 KB
    cudaFuncSetAttribute(k_layer2, cudaFuncAttributeMaxDynamicSharedMemorySize, smem2);

    k_fps<<<Bb, 512>>>(pos);
    k_ball<<<BM * 32 / 256, 256>>>(pos);
    k_count<<<1, 256>>>();
    k_layer1<<<BM, 256, smem1>>>(x, pos, W1, b1);
    k_bnstat<C1c><<<C1c, 256>>>(g1, be1);
    k_layer2<<<BM, 512, smem2>>>(W2, b2);
    k_bnstat<C2c><<<C2c, 256>>>(g2, be2);
    k_pool<<<BM, 128>>>(out);
    k_meta<<<(BM + 255) / 256, 256>>>(out);
}

// round 17
// speedup vs baseline: 1.1042x; 1.1042x over previous
#include <cuda_runtime.h>
#include <math.h>
#include <stdint.h>

// Problem constants
#define Bb   8
#define Nn   2048
#define Mm   1024
#define BM   8192          // B*M
#define Kk   64
#define Ff   64
#define C0c  67
#define C1c  64
#define C2c  128

// Output layout (float32, concatenated reference outputs)
#define OFF_POS   1048576   // BM*C2
#define OFF_BATCH 1073152   // + BM*3
#define OFF_IDX   1081344   // + BM

// ---------------- device scratch (static, no allocation) ----------------
__device__ int   g_idxLoc[BM];
__device__ float g_qpos[BM * 3];
__device__ int   g_nbr[BM * Kk];
__device__ int   g_cnt[BM];
__device__ int   g_V;
// h1 stored TRANSPOSED: [bm][c][k]  (c = channel 0..63, k = edge 0..63)
__device__ float g_h1[BM * Kk * C1c];           // 128 MB
__device__ float g_hmax[BM * C2c];              // masked max of h2 (pre-BN)
__device__ float g_hmin[BM * C2c];              // masked min of h2 (pre-BN)
__device__ float g_ps1[BM * C1c], g_pq1[BM * C1c];
__device__ float g_ps2[BM * C2c], g_pq2[BM * C2c];
__device__ float g_a1[C1c], g_o1[C1c], g_a2[C2c], g_o2[C2c];

// Strict (non-contracted) squared distance — must match XLA's fp32 mul/add
__device__ __forceinline__ float dist2s(float ax, float ay, float az,
                                        float bx, float by, float bz) {
    float dx = ax - bx, dy = ay - by, dz = az - bz;
    return __fadd_rn(__fadd_rn(__fmul_rn(dx, dx), __fmul_rn(dy, dy)),
                     __fmul_rn(dz, dz));
}

// Packed fp32x2 FMA (Blackwell sm_100+; per-lane .rn — bitwise == scalar fmaf)
#define FMA_F32X2(d, a, b, c) \
    asm("fma.rn.f32x2 %0, %1, %2, %3;" : "=l"(d) : "l"(a), "l"(b), "l"(c))
#define PACK2(d, v) \
    asm("mov.b64 %0, {%1, %1};" : "=l"(d) : "r"(__float_as_uint(v)))
#define UNPACK2(lo, hi, p) do {                                              \
    unsigned _ulo, _uhi;                                                     \
    asm("mov.b64 {%0, %1}, %2;" : "=r"(_ulo), "=r"(_uhi) : "l"(p));          \
    lo = __uint_as_float(_ulo); hi = __uint_as_float(_uhi);                  \
} while (0)

#define U64MAX(a, b) (((a) > (b)) ? (a) : (b))

// ---------------- K1: farthest point sampling (1 block / batch) ----------------
// 512 threads, 4 points/thread (R15 form) with ONE change: the 16 same-address
// smem atomics (serialized ~32cyc/warp = ~512cyc drain on the barrier) are
// scattered over 4 slots (wid&3) in 4 distinct bank pairs -> ~4x parallel
// drain. Post-barrier combine is O(1): 2 broadcast LDS.128 + 3 u64-max.
// Partition max-of-maxima == global max key -> identical tie semantics
// (max value, then lowest index). Triple-buffered slot groups, same reset
// schedule as R15 (read 2 epochs ago, written next epoch).
__global__ void __launch_bounds__(512) k_fps(const float* __restrict__ pos) {
    const int b = blockIdx.x;
    const int tid = threadIdx.x;
    __shared__ float4 sxyz[Nn];
    __shared__ __align__(16) unsigned long long skey[3][4];

    const float* p = pos + (size_t)b * Nn * 3;
    for (int i = tid; i < Nn; i += 512) {
        sxyz[i] = make_float4(p[i * 3 + 0], p[i * 3 + 1], p[i * 3 + 2], 0.f);
    }
    if (tid < 12) skey[tid >> 2][tid & 3] = 0ull;
    __syncthreads();

    const int i0 = tid, i1 = tid + 512, i2 = tid + 1024, i3 = tid + 1536;
    const float4 p0 = sxyz[i0], p1 = sxyz[i1], p2 = sxyz[i2], p3 = sxyz[i3];

    float4 c = sxyz[0];
    float m0 = dist2s(p0.x, p0.y, p0.z, c.x, c.y, c.z);
    float m1 = dist2s(p1.x, p1.y, p1.z, c.x, c.y, c.z);
    float m2 = dist2s(p2.x, p2.y, p2.z, c.x, c.y, c.z);
    float m3 = dist2s(p3.x, p3.y, p3.z, c.x, c.y, c.z);

    if (tid == 0) {
        g_idxLoc[b * Mm] = 0;
        float* qp = g_qpos + (size_t)(b * Mm) * 3;
        qp[0] = c.x; qp[1] = c.y; qp[2] = c.z;
    }
    const int wid = tid >> 5;
    const int lane = tid & 31;

    for (int t = 1; t < Mm; ++t) {
        // value-only local tournament (FMNMX)
        float bv = fmaxf(fmaxf(m0, m1), fmaxf(m2, m3));
        unsigned vbits = __float_as_uint(bv);   // distances >= 0: monotone as u32
        unsigned rv;
        asm("redux.sync.max.u32 %0, %1, 0xffffffff;" : "=r"(rv) : "r"(vbits));
        // lowest local index holding the max (i0 < i1 < i2 < i3)
        int bi = (m0 == bv) ? i0 : (m1 == bv) ? i1 : (m2 == bv) ? i2 : i3;
        unsigned cand = (vbits == rv) ? (unsigned)bi : 0xffffffffu;
        unsigned ri;
        asm("redux.sync.min.u32 %0, %1, 0xffffffff;" : "=r"(ri) : "r"(cand));
        const int slot = t % 3;
        if (lane == 0) {
            unsigned long long key =
                ((unsigned long long)rv << 32) | (unsigned)(Nn - (int)ri);
            atomicMax(&skey[slot][wid & 3], key);   // 4-way scattered drain
        }
        __syncthreads();
        const ulonglong2* kp = (const ulonglong2*)skey[slot];
        ulonglong2 ka = kp[0], kb = kp[1];
        unsigned long long best = U64MAX(U64MAX(ka.x, ka.y), U64MAX(kb.x, kb.y));
        if (tid < 4) skey[(t + 2) % 3][tid] = 0ull;   // safe: see header comment
        int nxt = Nn - (int)(unsigned int)(best & 0xffffffffu);
        c = sxyz[nxt];                             // one LDS.128 broadcast
        if (tid == 0) {
            g_idxLoc[b * Mm + t] = nxt;
            float* qp = g_qpos + (size_t)(b * Mm + t) * 3;
            qp[0] = c.x; qp[1] = c.y; qp[2] = c.z;
        }
        m0 = fminf(m0, dist2s(p0.x, p0.y, p0.z, c.x, c.y, c.z));
        m1 = fminf(m1, dist2s(p1.x, p1.y, p1.z, c.x, c.y, c.z));
        m2 = fminf(m2, dist2s(p2.x, p2.y, p2.z, c.x, c.y, c.z));
        m3 = fminf(m3, dist2s(p3.x, p3.y, p3.z, c.x, c.y, c.z));
    }
}

// ---------------- K2: ball query, first K in index order (1 warp / center) ----------------
__global__ void __launch_bounds__(256) k_ball(const float* __restrict__ pos) {
    int gw = (blockIdx.x * blockDim.x + threadIdx.x) >> 5;
    if (gw >= BM) return;
    const int lane = threadIdx.x & 31;
    const int b = gw >> 10;
    const float* p = pos + (size_t)b * Nn * 3;
    const float qx = g_qpos[gw * 3 + 0];
    const float qy = g_qpos[gw * 3 + 1];
    const float qz = g_qpos[gw * 3 + 2];
    int cnt = 0;
    for (int base = 0; base < Nn; base += 32) {
        int i = base + lane;
        float px = p[i * 3 + 0], py = p[i * 3 + 1], pz = p[i * 3 + 2];
        float d2 = dist2s(px, py, pz, qx, qy, qz);
        bool in = (d2 <= 0.04f);   // float32(R*R), same promotion as reference
        unsigned mask = __ballot_sync(0xffffffffu, in);
        int pre = __popc(mask & ((1u << lane) - 1u));
        int pp2 = cnt + pre;
        if (in && pp2 < Kk) g_nbr[gw * Kk + pp2] = i;
        cnt += __popc(mask);
        if (cnt >= Kk) break;
    }
    if (lane == 0) g_cnt[gw] = (cnt < Kk) ? cnt : Kk;
}

// ---------------- count total valid edges ----------------
__global__ void __launch_bounds__(256) k_count() {
    __shared__ int sr[256];
    int tid = threadIdx.x;
    int s = 0;
    for (int i = tid; i < BM; i += 256) s += g_cnt[i];
    sr[tid] = s; __syncthreads();
    for (int st = 128; st; st >>= 1) {
        if (tid < st) sr[tid] += sr[tid + st];
        __syncthreads();
    }
    if (tid == 0) g_V = sr[0];
}

// ---------------- K3: layer-1 (67->64) + partial BN1 stats ----------------
// R8's measured-best form (149.6us): 256 thr; tile 4c x 4e; pipelined j-loop.
#define FT_STRIDE 68
#define RED1_STR  68
__global__ void __launch_bounds__(256, 5) k_layer1(
    const float* __restrict__ x, const float* __restrict__ pos,
    const float* __restrict__ W1, const float* __restrict__ b1) {
    extern __shared__ float smem[];
    float* featT = smem;                        // [67][68] = 4556 floats
    float* W1s   = featT + C0c * FT_STRIDE;     // [67][64]
    float* redS  = featT;                       // alias: [16][68]
    float* redQ  = featT + 16 * RED1_STR;       // alias: [16][68]
    __shared__ int snbr[Kk];

    const int bm = blockIdx.x;
    const int b = bm >> 10;
    const int tid = threadIdx.x;
    const int cnt = g_cnt[bm];

    if (tid < Kk) snbr[tid] = (tid < cnt) ? g_nbr[bm * Kk + tid] : 0;
    for (int e = tid; e < C0c * C1c; e += 256) W1s[e] = W1[e];
    __syncthreads();

    const float* xb = x + (size_t)b * Nn * Ff;
    for (int e = tid; e < cnt * Ff; e += 256) {
        int k = e >> 6, j = e & 63;
        featT[j * FT_STRIDE + k] = xb[(size_t)snbr[k] * Ff + j];
    }
    if (tid < cnt) {
        int k = tid, n = snbr[k];
        const float* pp = pos + ((size_t)b * Nn + n) * 3;
        const float* qq = g_qpos + (size_t)bm * 3;
        featT[64 * FT_STRIDE + k] = pp[0] - qq[0];
        featT[65 * FT_STRIDE + k] = pp[1] - qq[1];
        featT[66 * FT_STRIDE + k] = pp[2] - qq[2];
    }
    __syncthreads();

    const int eg = (tid & 15) * 4;
    const int cg = (tid >> 4) * 4;
    float ps[4] = {0.f, 0.f, 0.f, 0.f};
    float pq[4] = {0.f, 0.f, 0.f, 0.f};
    if (eg < cnt) {
        unsigned long long acc[8];
        float4 b4 = *(const float4*)(b1 + cg);
        PACK2(acc[0], b4.x); acc[1] = acc[0];
        PACK2(acc[2], b4.y); acc[3] = acc[2];
        PACK2(acc[4], b4.z); acc[5] = acc[4];
        PACK2(acc[6], b4.w); acc[7] = acc[6];
        const float* wr = W1s + cg;
        const float* fr = featT + eg;
        float4 w4 = *(const float4*)(wr);
        ulonglong2 f = *(const ulonglong2*)(fr);
        #pragma unroll 4
        for (int j = 0; j < C0c - 1; j++) {
            float4 w4n = *(const float4*)(wr + (j + 1) * C1c);
            ulonglong2 fn = *(const ulonglong2*)(fr + (j + 1) * FT_STRIDE);
            unsigned long long w0, w1, w2, w3;
            PACK2(w0, w4.x); PACK2(w1, w4.y); PACK2(w2, w4.z); PACK2(w3, w4.w);
            FMA_F32X2(acc[0], f.x, w0, acc[0]);
            FMA_F32X2(acc[1], f.y, w0, acc[1]);
            FMA_F32X2(acc[2], f.x, w1, acc[2]);
            FMA_F32X2(acc[3], f.y, w1, acc[3]);
            FMA_F32X2(acc[4], f.x, w2, acc[4]);
            FMA_F32X2(acc[5], f.y, w2, acc[5]);
            FMA_F32X2(acc[6], f.x, w3, acc[6]);
            FMA_F32X2(acc[7], f.y, w3, acc[7]);
            w4 = w4n; f = fn;
        }
        {   // tail j = C0c-1
            unsigned long long w0, w1, w2, w3;
            PACK2(w0, w4.x); PACK2(w1, w4.y); PACK2(w2, w4.z); PACK2(w3, w4.w);
            FMA_F32X2(acc[0], f.x, w0, acc[0]);
            FMA_F32X2(acc[1], f.y, w0, acc[1]);
            FMA_F32X2(acc[2], f.x, w1, acc[2]);
            FMA_F32X2(acc[3], f.y, w1, acc[3]);
            FMA_F32X2(acc[4], f.x, w2, acc[4]);
            FMA_F32X2(acc[5], f.y, w2, acc[5]);
            FMA_F32X2(acc[6], f.x, w3, acc[6]);
            FMA_F32X2(acc[7], f.y, w3, acc[7]);
        }
        float* outb = g_h1 + (size_t)bm * (Kk * C1c);
        #pragma unroll
        for (int ch = 0; ch < 4; ch++) {
            float h0, h1, h2, h3;
            UNPACK2(h0, h1, acc[2 * ch]);
            UNPACK2(h2, h3, acc[2 * ch + 1]);
            h0 = fmaxf(h0, 0.f); h1 = fmaxf(h1, 0.f);
            h2 = fmaxf(h2, 0.f); h3 = fmaxf(h3, 0.f);
            *(float4*)(outb + (cg + ch) * Kk + eg) = make_float4(h0, h1, h2, h3);
            float hv[4] = {h0, h1, h2, h3};
            #pragma unroll
            for (int t = 0; t < 4; t++) {
                if (eg + t < cnt) { ps[ch] += hv[t]; pq[ch] += hv[t] * hv[t]; }
            }
        }
    }
    __syncthreads();   // all featT reads done before aliased red writes
    *(float4*)(redS + (tid & 15) * RED1_STR + cg) = make_float4(ps[0], ps[1], ps[2], ps[3]);
    *(float4*)(redQ + (tid & 15) * RED1_STR + cg) = make_float4(pq[0], pq[1], pq[2], pq[3]);
    __syncthreads();
    if (tid < C1c) {
        float s = 0.f, q = 0.f;
        #pragma unroll
        for (int g = 0; g < 16; g++) {
            s += redS[g * RED1_STR + tid];
            q += redQ[g * RED1_STR + tid];
        }
        g_ps1[(size_t)bm * C1c + tid] = s;
        g_pq1[(size_t)bm * C1c + tid] = q;
    }
}

// ---------------- BN stat reduction (deterministic, double) ----------------
template <int C>
__global__ void __launch_bounds__(256) k_bnstat(const float* __restrict__ gamma,
                                                const float* __restrict__ beta) {
    const float* ps = (C == C1c) ? g_ps1 : g_ps2;
    const float* pq = (C == C1c) ? g_pq1 : g_pq2;
    float* a = (C == C1c) ? g_a1 : g_a2;
    float* o = (C == C1c) ? g_o1 : g_o2;
    const int c = blockIdx.x, tid = threadIdx.x;
    __shared__ double ss[256], sq[256];
    double s = 0.0, q = 0.0;
    for (int i = tid; i < BM; i += 256) {
        s += (double)ps[(size_t)i * C + c];
        q += (double)pq[(size_t)i * C + c];
    }
    ss[tid] = s; sq[tid] = q; __syncthreads();
    for (int st = 128; st; st >>= 1) {
        if (tid < st) { ss[tid] += ss[tid + st]; sq[tid] += sq[tid + st]; }
        __syncthreads();
    }
    if (tid == 0) {
        double V = (double)g_V;
        double mean = ss[0] / V;
        double var = sq[0] / V - mean * mean;
        float af = gamma[c] * rsqrtf((float)var + 1e-5f);
        a[c] = af;
        o[c] = beta[c] - (float)mean * af;
    }
}

// ---------------- K5: BN1-apply + layer-2 (64->128) + BN2 stats + pooled extremes ----------
// R15's measured-best form: 512 thr, tile 4c x 4e, reduction buffers aliased
// over h1ns => 50.2 KB smem, 4 blocks/SM (100% occ), regs 32 ((512,4)).
#define RED2_STR 132
__global__ void __launch_bounds__(512, 4) k_layer2(const float* __restrict__ W2,
                                                   const float* __restrict__ b2) {
    extern __shared__ float smem[];
    float* h1ns = smem;                         // [64][68] = 4352 floats
    float* W2s  = h1ns + C1c * FT_STRIDE;       // [64][128]
    float* redA = h1ns;                         // alias: [16][132] = 2112
    float* redB = h1ns + 16 * RED2_STR;         // alias: 2112 (4224 <= 4352 ok)
    __shared__ float a1s[C1c], o1s[C1c];

    const int bm = blockIdx.x;
    const int tid = threadIdx.x;
    const int cnt = g_cnt[bm];

    if (tid < C1c) { a1s[tid] = g_a1[tid]; o1s[tid] = g_o1[tid]; }
    for (int e = tid; e < C1c * C2c; e += 512) W2s[e] = W2[e];
    __syncthreads();

    const float* h1p = g_h1 + (size_t)bm * (Kk * C1c);   // [j][k] layout
    for (int e = tid; e < C1c * Kk; e += 512) {
        int j = e >> 6, k = e & 63;
        h1ns[j * FT_STRIDE + k] = h1p[e] * a1s[j] + o1s[j];   // conflict-free STS
    }
    __syncthreads();

    const int eg = (tid & 15) * 4;
    const int cg = (tid >> 4) * 4;          // 0..124
    float ps[4]  = {0.f, 0.f, 0.f, 0.f};
    float pq[4]  = {0.f, 0.f, 0.f, 0.f};
    float pmx[4] = {-INFINITY, -INFINITY, -INFINITY, -INFINITY};
    float pmn[4] = { INFINITY,  INFINITY,  INFINITY,  INFINITY};
    if (eg < cnt) {
        unsigned long long acc[8];
        float4 b4 = *(const float4*)(b2 + cg);
        PACK2(acc[0], b4.x); acc[1] = acc[0];
        PACK2(acc[2], b4.y); acc[3] = acc[2];
        PACK2(acc[4], b4.z); acc[5] = acc[4];
        PACK2(acc[6], b4.w); acc[7] = acc[6];
        #pragma unroll 4
        for (int j = 0; j < C1c; j++) {
            float4 w4 = *(const float4*)(W2s + j * C2c + cg);
            ulonglong2 f = *(const ulonglong2*)(h1ns + j * FT_STRIDE + eg);
            unsigned long long w0, w1, w2, w3;
            PACK2(w0, w4.x); PACK2(w1, w4.y); PACK2(w2, w4.z); PACK2(w3, w4.w);
            FMA_F32X2(acc[0], f.x, w0, acc[0]);
            FMA_F32X2(acc[1], f.y, w0, acc[1]);
            FMA_F32X2(acc[2], f.x, w1, acc[2]);
            FMA_F32X2(acc[3], f.y, w1, acc[3]);
            FMA_F32X2(acc[4], f.x, w2, acc[4]);
            FMA_F32X2(acc[5], f.y, w2, acc[5]);
            FMA_F32X2(acc[6], f.x, w3, acc[6]);
            FMA_F32X2(acc[7], f.y, w3, acc[7]);
        }
        #pragma unroll
        for (int ch = 0; ch < 4; ch++) {
            float h0, h1, h2, h3;
            UNPACK2(h0, h1, acc[2 * ch]);
            UNPACK2(h2, h3, acc[2 * ch + 1]);
            float hv[4] = {fmaxf(h0, 0.f), fmaxf(h1, 0.f),
                           fmaxf(h2, 0.f), fmaxf(h3, 0.f)};
            #pragma unroll
            for (int t = 0; t < 4; t++) {
                if (eg + t < cnt) {
                    ps[ch] += hv[t]; pq[ch] += hv[t] * hv[t];
                    pmx[ch] = fmaxf(pmx[ch], hv[t]);
                    pmn[ch] = fminf(pmn[ch], hv[t]);
                }
            }
        }
    }
    // round 1: sum & sumsq (red aliases h1ns — barrier after last h1ns read)
    __syncthreads();
    *(float4*)(redA + (tid & 15) * RED2_STR + cg) = make_float4(ps[0], ps[1], ps[2], ps[3]);
    *(float4*)(redB + (tid & 15) * RED2_STR + cg) = make_float4(pq[0], pq[1], pq[2], pq[3]);
    __syncthreads();
    if (tid < C2c) {
        float s = 0.f, q = 0.f;
        #pragma unroll
        for (int g = 0; g < 16; g++) {
            s += redA[g * RED2_STR + tid];
            q += redB[g * RED2_STR + tid];
        }
        g_ps2[(size_t)bm * C2c + tid] = s;
        g_pq2[(size_t)bm * C2c + tid] = q;
    }
    __syncthreads();
    // round 2: max & min
    *(float4*)(redA + (tid & 15) * RED2_STR + cg) = make_float4(pmx[0], pmx[1], pmx[2], pmx[3]);
    *(float4*)(redB + (tid & 15) * RED2_STR + cg) = make_float4(pmn[0], pmn[1], pmn[2], pmn[3]);
    __syncthreads();
    if (tid < C2c) {
        float mx = -INFINITY, mn = INFINITY;
        #pragma unroll
        for (int g = 0; g < 16; g++) {
            mx = fmaxf(mx, redA[g * RED2_STR + tid]);
            mn = fminf(mn, redB[g * RED2_STR + tid]);
        }
        g_hmax[(size_t)bm * C2c + tid] = mx;
        g_hmin[(size_t)bm * C2c + tid] = mn;
    }
}

// ---------------- K7: pooled BN2-apply ----------------
// max_k(a*h+o) == a*max_k(h)+o for a>=0, a*min_k(h)+o for a<0 (monotone fp ops,
// bitwise identical to elementwise-then-max). cnt>=1 always (center in-ball).
__global__ void __launch_bounds__(128) k_pool(float* __restrict__ out) {
    const int bm = blockIdx.x;
    const int c = threadIdx.x;
    const float a = g_a2[c], o = g_o2[c];
    const float h = (a >= 0.f) ? g_hmax[(size_t)bm * C2c + c]
                               : g_hmin[(size_t)bm * C2c + c];
    out[(size_t)bm * C2c + c] = a * h + o;
}

// ---------------- meta outputs: pos_out, batch_out, idx_glob ----------------
__global__ void __launch_bounds__(256) k_meta(float* __restrict__ out) {
    int i = blockIdx.x * blockDim.x + threadIdx.x;
    if (i >= BM) return;
    int b = i >> 10;
    out[OFF_POS + i * 3 + 0] = g_qpos[i * 3 + 0];
    out[OFF_POS + i * 3 + 1] = g_qpos[i * 3 + 1];
    out[OFF_POS + i * 3 + 2] = g_qpos[i * 3 + 2];
    out[OFF_BATCH + i] = (float)b;
    out[OFF_IDX + i] = (float)(g_idxLoc[i] + b * Nn);
}

// ---------------- host launcher ----------------
extern "C" void kernel_launch(void* const* d_in, const int* in_sizes, int n_in,
                              void* d_out, int out_size) {
    const float* x   = (const float*)d_in[0];
    const float* pos = (const float*)d_in[1];
    // d_in[2] = batch (unused; recomputed analytically)
    const float* W1  = (const float*)d_in[3];
    const float* b1  = (const float*)d_in[4];
    const float* g1  = (const float*)d_in[5];
    const float* be1 = (const float*)d_in[6];
    const float* W2  = (const float*)d_in[7];
    const float* b2  = (const float*)d_in[8];
    const float* g2  = (const float*)d_in[9];
    const float* be2 = (const float*)d_in[10];
    float* out = (float*)d_out;

    const int smem1 = (C0c * FT_STRIDE + C0c * C1c) * (int)sizeof(float);   // 35.4 KB
    const int smem2 = (C1c * FT_STRIDE + C1c * C2c) * (int)sizeof(float);   // 50.2 KB
    cudaFuncSetAttribute(k_layer2, cudaFuncAttributeMaxDynamicSharedMemorySize, smem2);

    k_fps<<<Bb, 512>>>(pos);
    k_ball<<<BM * 32 / 256, 256>>>(pos);
    k_count<<<1, 256>>>();
    k_layer1<<<BM, 256, smem1>>>(x, pos, W1, b1);
    k_bnstat<C1c><<<C1c, 256>>>(g1, be1);
    k_layer2<<<BM, 512, smem2>>>(W2, b2);
    k_bnstat<C2c><<<C2c, 256>>>(g2, be2);
    k_pool<<<BM, 128>>>(out);
    k_meta<<<(BM + 255) / 256, 256>>>(out);
}